// round 14
// baseline (speedup 1.0000x reference)
#include <cuda_runtime.h>
#include <cuda_fp16.h>
#include <cstdint>

// ============================================================================
// y[M,N] = x[M,K] @ (qw*sw)^T + bias   M=8192, N=4096, K=4096
// x fp32, qw int32 (int8 values), sw fp32 scalar, bias fp32[N], out fp32.
//
// compute_103 target (no tcgen05) => mma.sync.m16n8k16 fp16 / fp32 accum.
// Weights EXACT in fp16 (|q|<=128); x->fp16 gives rel_err ~2e-4 < 1e-3.
//
// R13 vs R10 (628.8us):
//  - produce(next) moved BEFORE tile compute (loads start ~1 k-iter earlier)
//  - empty released right after last kstep's ldmatrix (smem dead for MMAs)
//  - conversion kernels: grid-stride, 4 independent float4/iter (MLP>=4)
// ============================================================================

#define MDIM 8192
#define NDIM 4096
#define KDIM 4096

#define BM 128
#define BN 128
#define BK 64
#define STAGES 3
#define KITERS (KDIM / BK)          // 64

#define ROW_HALFS (BK + 8)           // 72 halfs = 144 B (conflict-free ldmatrix)
#define ROW_BYTES (ROW_HALFS * 2)
#define A_STAGE_BYTES (BM * ROW_BYTES)             // 18432
#define B_STAGE_BYTES (BN * ROW_BYTES)             // 18432
#define STAGE_BYTES (A_STAGE_BYTES + B_STAGE_BYTES)  // 36864
#define SMEM_TOTAL (STAGES * STAGE_BYTES)            // 110592 B -> 2 CTAs/SM

// ---------------- scratch (static device globals: allocation-free) ----------
__device__ __half g_xh[(size_t)MDIM * KDIM];  // 64 MB
__device__ __half g_w[(size_t)NDIM * KDIM];   // 32 MB

// ---------------- mbarrier helpers (sm_80+ generic PTX) ----------------------
#define MBAR_INIT(addr, count) \
    asm volatile("mbarrier.init.shared.b64 [%0], %1;" \
        :: "r"((uint32_t)(addr)), "r"((uint32_t)(count)) : "memory")

#define MBAR_ARRIVE(addr) \
    asm volatile("mbarrier.arrive.shared.b64 _, [%0];" :: "r"((uint32_t)(addr)) : "memory")

// NOINC: the completion arrive COUNTS against the init count (256).
#define CPASYNC_MBAR_ARRIVE_NOINC(addr) \
    asm volatile("cp.async.mbarrier.arrive.noinc.shared.b64 [%0];" \
        :: "r"((uint32_t)(addr)) : "memory")

#define MBAR_WAIT_PARITY(mbar_addr, phase_parity) do { \
    uint32_t _mbar = (uint32_t)(mbar_addr); \
    uint32_t _par = (uint32_t)(phase_parity); \
    uint32_t _done; \
    asm volatile( \
        "{\n\t.reg .pred p;\n\t" \
        "mbarrier.try_wait.parity.shared.b64 p, [%1], %2, 0x989680;\n\t" \
        "selp.b32 %0, 1, 0, p;\n\t}" \
        : "=r"(_done) : "r"(_mbar), "r"(_par) : "memory"); \
    if (!_done) { \
        asm volatile( \
            "{\n\t.reg .pred P1;\n\t" \
            "WL_%=:\n\t" \
            "mbarrier.try_wait.parity.shared.b64 P1, [%0], %1, 0x989680;\n\t" \
            "@P1 bra.uni WD_%=;\n\t" \
            "bra.uni WL_%=;\n\t" \
            "WD_%=:\n\t}" \
            :: "r"(_mbar), "r"(_par) : "memory"); \
    } \
} while (0)

// ---------------- conversion kernels (grid-stride, MLP=4) --------------------
__global__ __launch_bounds__(256) void convert_w_kernel(const int* __restrict__ qw) {
    const size_t n4 = (size_t)NDIM * KDIM / 4;           // int4 count
    const size_t stride = (size_t)gridDim.x * blockDim.x;
    __half2* w2 = reinterpret_cast<__half2*>(g_w);
    for (size_t i = (size_t)blockIdx.x * blockDim.x + threadIdx.x; i < n4; i += stride * 4) {
        int4 v[4];
        size_t idx[4];
#pragma unroll
        for (int j = 0; j < 4; ++j) {
            idx[j] = i + j * stride;
            if (idx[j] < n4) v[j] = reinterpret_cast<const int4*>(qw)[idx[j]];
        }
#pragma unroll
        for (int j = 0; j < 4; ++j) {
            if (idx[j] < n4) {
                w2[2 * idx[j] + 0] = __floats2half2_rn((float)v[j].x, (float)v[j].y);
                w2[2 * idx[j] + 1] = __floats2half2_rn((float)v[j].z, (float)v[j].w);
            }
        }
    }
}

__global__ __launch_bounds__(256) void convert_x_kernel(const float* __restrict__ x) {
    const size_t n4 = (size_t)MDIM * KDIM / 4;           // float4 count
    const size_t stride = (size_t)gridDim.x * blockDim.x;
    __half2* xh2 = reinterpret_cast<__half2*>(g_xh);
    for (size_t i = (size_t)blockIdx.x * blockDim.x + threadIdx.x; i < n4; i += stride * 4) {
        float4 v[4];
        size_t idx[4];
#pragma unroll
        for (int j = 0; j < 4; ++j) {
            idx[j] = i + j * stride;
            if (idx[j] < n4) v[j] = reinterpret_cast<const float4*>(x)[idx[j]];
        }
#pragma unroll
        for (int j = 0; j < 4; ++j) {
            if (idx[j] < n4) {
                xh2[2 * idx[j] + 0] = __floats2half2_rn(v[j].x, v[j].y);
                xh2[2 * idx[j] + 1] = __floats2half2_rn(v[j].z, v[j].w);
            }
        }
    }
}

// ---------------- GEMM kernel ------------------------------------------------
__global__ __launch_bounds__(256, 2) void gemm_kernel(
    float* __restrict__ out,
    const float* __restrict__ swp,
    const float* __restrict__ bias) {
    extern __shared__ char smem[];
    __shared__ unsigned long long mb_full[STAGES];
    __shared__ unsigned long long mb_empty[STAGES];

    const int tid = threadIdx.x;
    const int lane = tid & 31;
    const int wid = tid >> 5;
    const int wm = (wid & 1) * 64;   // 2 warps in m, 64 rows each
    const int wn = (wid >> 1) * 32;  // 4 warps in n, 32 cols each
    const int m0 = blockIdx.y * BM;
    const int n0 = blockIdx.x * BN;

    const uint32_t sbase = (uint32_t)__cvta_generic_to_shared(smem);
    uint32_t full_a[STAGES], empty_a[STAGES];
#pragma unroll
    for (int s = 0; s < STAGES; ++s) {
        full_a[s] = (uint32_t)__cvta_generic_to_shared(&mb_full[s]);
        empty_a[s] = (uint32_t)__cvta_generic_to_shared(&mb_empty[s]);
    }

    if (tid == 0) {
#pragma unroll
        for (int s = 0; s < STAGES; ++s) {
            MBAR_INIT(full_a[s], 256);  // one NOINC completion-arrive per thread
            MBAR_INIT(empty_a[s], 8);   // one arrive per consumer warp
        }
    }
    __syncthreads();

    const __half* gA = g_xh + (size_t)m0 * KDIM;
    const __half* gW = g_w + (size_t)n0 * KDIM;

    float acc[4][4][4];
#pragma unroll
    for (int mi = 0; mi < 4; ++mi)
#pragma unroll
        for (int n = 0; n < 4; ++n)
#pragma unroll
            for (int j = 0; j < 4; ++j) acc[mi][n][j] = 0.f;

    // Per-thread LDSM base offsets
    const uint32_t a_row_off = (lane & 15) * ROW_BYTES + (lane >> 4) * 16;        // +k*2
    const uint32_t b_row_off = (((lane >> 4) & 1) * 8 + (lane & 7)) * ROW_BYTES
                               + (((lane >> 3) & 1) * 8) * 2;                      // +k*2

    // ---- producer body: cp.async tile `it` into stage `s`, noinc-arrive full
    auto produce = [&](int it, int s) {
        const int k0 = it * BK;
        const uint32_t As = sbase + s * STAGE_BYTES;
        const uint32_t Bs = As + A_STAGE_BYTES;
#pragma unroll
        for (int i = 0; i < 4; ++i) {           // A: 1024 16B chunks, 4/thread
            const int c = tid + i * 256;
            const int r = c >> 3, cc = c & 7;
            const uint32_t d = As + r * ROW_BYTES + cc * 16;
            const size_t gsrc = __cvta_generic_to_global(gA + (size_t)r * KDIM + k0 + cc * 8);
            asm volatile("cp.async.cg.shared.global [%0], [%1], 16;"
                         :: "r"(d), "l"(gsrc) : "memory");
        }
#pragma unroll
        for (int i = 0; i < 4; ++i) {           // B: 1024 chunks, 4/thread
            const int c = tid + i * 256;
            const int r = c >> 3, cc = c & 7;
            const uint32_t d = Bs + r * ROW_BYTES + cc * 16;
            const size_t gsrc = __cvta_generic_to_global(gW + (size_t)r * KDIM + k0 + cc * 8);
            asm volatile("cp.async.cg.shared.global [%0], [%1], 16;"
                         :: "r"(d), "l"(gsrc) : "memory");
        }
        CPASYNC_MBAR_ARRIVE_NOINC(full_a[s]);
    };

    // ---- prologue ------------------------------------------------------------
    int p_stage = 0, p_phase = 1;
#pragma unroll
    for (int it = 0; it < STAGES - 1; ++it) {
        MBAR_WAIT_PARITY(empty_a[p_stage], p_phase);  // passes immediately round 0
        produce(it, p_stage);
        if (++p_stage == STAGES) { p_stage = 0; p_phase ^= 1; }
    }

    int c_stage = 0, c_phase = 0;

    // ---- mainloop ------------------------------------------------------------
    for (int it = 0; it < KITERS; ++it) {
        MBAR_WAIT_PARITY(full_a[c_stage], c_phase);

        // Issue next tile's loads BEFORE computing this tile: loads overlap
        // the whole tile compute instead of starting after it.
        const int nt = it + (STAGES - 1);
        if (nt < KITERS) {
            MBAR_WAIT_PARITY(empty_a[p_stage], p_phase);
            produce(nt, p_stage);
            if (++p_stage == STAGES) { p_stage = 0; p_phase ^= 1; }
        }

        const uint32_t As = sbase + c_stage * STAGE_BYTES;
        const uint32_t Bs = As + A_STAGE_BYTES;

#pragma unroll
        for (int ks = 0; ks < BK / 16; ++ks) {
            const uint32_t kb = ks * 32;  // bytes along k
            uint32_t a[4][4], b[2][4];
#pragma unroll
            for (int mi = 0; mi < 4; ++mi) {
                const uint32_t ad = As + (wm + mi * 16) * ROW_BYTES + a_row_off + kb;
                asm volatile("ldmatrix.sync.aligned.m8n8.x4.shared.b16 {%0,%1,%2,%3}, [%4];"
                             : "=r"(a[mi][0]), "=r"(a[mi][1]), "=r"(a[mi][2]), "=r"(a[mi][3])
                             : "r"(ad));
            }
#pragma unroll
            for (int nj = 0; nj < 2; ++nj) {
                const uint32_t bd = Bs + (wn + nj * 16) * ROW_BYTES + b_row_off + kb;
                asm volatile("ldmatrix.sync.aligned.m8n8.x4.shared.b16 {%0,%1,%2,%3}, [%4];"
                             : "=r"(b[nj][0]), "=r"(b[nj][1]), "=r"(b[nj][2]), "=r"(b[nj][3])
                             : "r"(bd));
            }
            // After the LAST kstep's ldmatrix, smem for this stage is dead:
            // release it before doing the (register-only) MMAs.
            if (ks == BK / 16 - 1) {
                if (lane == 0) MBAR_ARRIVE(empty_a[c_stage]);
            }
#pragma unroll
            for (int mi = 0; mi < 4; ++mi) {
#pragma unroll
                for (int n = 0; n < 4; ++n) {
                    float* c = acc[mi][n];
                    const uint32_t b0 = b[n >> 1][(n & 1) * 2];
                    const uint32_t b1 = b[n >> 1][(n & 1) * 2 + 1];
                    asm volatile(
                        "mma.sync.aligned.m16n8k16.row.col.f32.f16.f16.f32 "
                        "{%0,%1,%2,%3}, {%4,%5,%6,%7}, {%8,%9}, {%0,%1,%2,%3};"
                        : "+f"(c[0]), "+f"(c[1]), "+f"(c[2]), "+f"(c[3])
                        : "r"(a[mi][0]), "r"(a[mi][1]), "r"(a[mi][2]), "r"(a[mi][3]),
                          "r"(b0), "r"(b1));
                }
            }
        }

        if (++c_stage == STAGES) { c_stage = 0; c_phase ^= 1; }
    }

    // ---- epilogue: out = acc*sw + bias --------------------------------------
    const float swv = *swp;
#pragma unroll
    for (int mi = 0; mi < 4; ++mi) {
        const int mr = m0 + wm + mi * 16 + (lane >> 2);
        float* r0 = out + (size_t)mr * NDIM;
        float* r1 = out + (size_t)(mr + 8) * NDIM;
#pragma unroll
        for (int n = 0; n < 4; ++n) {
            const int nc = n0 + wn + n * 8 + (lane & 3) * 2;
            const float2 bv = *reinterpret_cast<const float2*>(bias + nc);
            float2 v0, v1;
            v0.x = acc[mi][n][0] * swv + bv.x;
            v0.y = acc[mi][n][1] * swv + bv.y;
            v1.x = acc[mi][n][2] * swv + bv.x;
            v1.y = acc[mi][n][3] * swv + bv.y;
            *reinterpret_cast<float2*>(r0 + nc) = v0;
            *reinterpret_cast<float2*>(r1 + nc) = v1;
        }
    }
}

// ---------------- launch -----------------------------------------------------
extern "C" void kernel_launch(void* const* d_in, const int* in_sizes, int n_in,
                              void* d_out, int out_size) {
    const float* x = (const float*)d_in[0];
    const int* qw = (const int*)d_in[1];
    const float* sw = (const float*)d_in[2];
    const float* bias = (const float*)d_in[3];
    float* out = (float*)d_out;
    (void)in_sizes; (void)n_in; (void)out_size;

    cudaFuncSetAttribute(gemm_kernel, cudaFuncAttributeMaxDynamicSharedMemorySize, SMEM_TOTAL);

    convert_w_kernel<<<1184, 256>>>(qw);   // 8 blocks/SM, grid-stride MLP=4
    convert_x_kernel<<<2368, 256>>>(x);    // 16 blocks/SM, grid-stride MLP=4

    dim3 grid(NDIM / BN, MDIM / BM);  // (32, 64)
    gemm_kernel<<<grid, 256, SMEM_TOTAL>>>(out, sw, bias);
}

// round 15
// speedup vs baseline: 1.6704x; 1.6704x over previous
#include <cuda_runtime.h>
#include <cuda_fp16.h>
#include <cstdint>

// ============================================================================
// y[M,N] = x[M,K] @ (qw*sw)^T + bias   M=8192, N=4096, K=4096
// x fp32, qw int32 (int8 values), sw fp32 scalar, bias fp32[N], out fp32.
//
// compute_103 target (no tcgen05) => mma.sync.m16n8k16 fp16 / fp32 accum.
// Weights EXACT in fp16 (|q|<=128); x->fp16 gives rel_err ~2e-4 < 1e-3.
//
// R14 = revert to R10 structure (628.8us) after R13 regression (1057us:
// produce-before-compute put 8 cp.asyncs ahead of the first ldmatrix in every
// warp's issue stream -> LSU/MIO serialization).
// Single retained tweak: empty barrier released right after the LAST kstep's
// ldmatrix (smem dead once frags are in regs) instead of after all MMAs.
// Conversion kernels: original simple form (16us, 57% DRAM).
// ============================================================================

#define MDIM 8192
#define NDIM 4096
#define KDIM 4096

#define BM 128
#define BN 128
#define BK 64
#define STAGES 3
#define KITERS (KDIM / BK)          // 64

#define ROW_HALFS (BK + 8)           // 72 halfs = 144 B (conflict-free ldmatrix)
#define ROW_BYTES (ROW_HALFS * 2)
#define A_STAGE_BYTES (BM * ROW_BYTES)             // 18432
#define B_STAGE_BYTES (BN * ROW_BYTES)             // 18432
#define STAGE_BYTES (A_STAGE_BYTES + B_STAGE_BYTES)  // 36864
#define SMEM_TOTAL (STAGES * STAGE_BYTES)            // 110592 B -> 2 CTAs/SM

// ---------------- scratch (static device globals: allocation-free) ----------
__device__ __half g_xh[(size_t)MDIM * KDIM];  // 64 MB
__device__ __half g_w[(size_t)NDIM * KDIM];   // 32 MB

// ---------------- mbarrier helpers (sm_80+ generic PTX) ----------------------
#define MBAR_INIT(addr, count) \
    asm volatile("mbarrier.init.shared.b64 [%0], %1;" \
        :: "r"((uint32_t)(addr)), "r"((uint32_t)(count)) : "memory")

#define MBAR_ARRIVE(addr) \
    asm volatile("mbarrier.arrive.shared.b64 _, [%0];" :: "r"((uint32_t)(addr)) : "memory")

// NOINC: the completion arrive COUNTS against the init count (256).
#define CPASYNC_MBAR_ARRIVE_NOINC(addr) \
    asm volatile("cp.async.mbarrier.arrive.noinc.shared.b64 [%0];" \
        :: "r"((uint32_t)(addr)) : "memory")

#define MBAR_WAIT_PARITY(mbar_addr, phase_parity) do { \
    uint32_t _mbar = (uint32_t)(mbar_addr); \
    uint32_t _par = (uint32_t)(phase_parity); \
    uint32_t _done; \
    asm volatile( \
        "{\n\t.reg .pred p;\n\t" \
        "mbarrier.try_wait.parity.shared.b64 p, [%1], %2, 0x989680;\n\t" \
        "selp.b32 %0, 1, 0, p;\n\t}" \
        : "=r"(_done) : "r"(_mbar), "r"(_par) : "memory"); \
    if (!_done) { \
        asm volatile( \
            "{\n\t.reg .pred P1;\n\t" \
            "WL_%=:\n\t" \
            "mbarrier.try_wait.parity.shared.b64 P1, [%0], %1, 0x989680;\n\t" \
            "@P1 bra.uni WD_%=;\n\t" \
            "bra.uni WL_%=;\n\t" \
            "WD_%=:\n\t}" \
            :: "r"(_mbar), "r"(_par) : "memory"); \
    } \
} while (0)

// ---------------- conversion kernels (original simple form) ------------------
__global__ __launch_bounds__(256) void convert_w_kernel(const int* __restrict__ qw) {
    size_t idx = (size_t)blockIdx.x * blockDim.x + threadIdx.x;  // one int4 (4 weights)
    const int4 v = reinterpret_cast<const int4*>(qw)[idx];
    __half2* w2 = reinterpret_cast<__half2*>(g_w);
    w2[2 * idx + 0] = __floats2half2_rn((float)v.x, (float)v.y);
    w2[2 * idx + 1] = __floats2half2_rn((float)v.z, (float)v.w);
}

__global__ __launch_bounds__(256) void convert_x_kernel(const float* __restrict__ x) {
    size_t idx = (size_t)blockIdx.x * blockDim.x + threadIdx.x;  // one float4
    const float4 v = reinterpret_cast<const float4*>(x)[idx];
    __half2* xh2 = reinterpret_cast<__half2*>(g_xh);
    xh2[2 * idx + 0] = __floats2half2_rn(v.x, v.y);
    xh2[2 * idx + 1] = __floats2half2_rn(v.z, v.w);
}

// ---------------- GEMM kernel ------------------------------------------------
__global__ __launch_bounds__(256, 2) void gemm_kernel(
    float* __restrict__ out,
    const float* __restrict__ swp,
    const float* __restrict__ bias) {
    extern __shared__ char smem[];
    __shared__ unsigned long long mb_full[STAGES];
    __shared__ unsigned long long mb_empty[STAGES];

    const int tid = threadIdx.x;
    const int lane = tid & 31;
    const int wid = tid >> 5;
    const int wm = (wid & 1) * 64;   // 2 warps in m, 64 rows each
    const int wn = (wid >> 1) * 32;  // 4 warps in n, 32 cols each
    const int m0 = blockIdx.y * BM;
    const int n0 = blockIdx.x * BN;

    const uint32_t sbase = (uint32_t)__cvta_generic_to_shared(smem);
    uint32_t full_a[STAGES], empty_a[STAGES];
#pragma unroll
    for (int s = 0; s < STAGES; ++s) {
        full_a[s] = (uint32_t)__cvta_generic_to_shared(&mb_full[s]);
        empty_a[s] = (uint32_t)__cvta_generic_to_shared(&mb_empty[s]);
    }

    if (tid == 0) {
#pragma unroll
        for (int s = 0; s < STAGES; ++s) {
            MBAR_INIT(full_a[s], 256);  // one NOINC completion-arrive per thread
            MBAR_INIT(empty_a[s], 8);   // one arrive per consumer warp
        }
    }
    __syncthreads();

    const __half* gA = g_xh + (size_t)m0 * KDIM;
    const __half* gW = g_w + (size_t)n0 * KDIM;

    float acc[4][4][4];
#pragma unroll
    for (int mi = 0; mi < 4; ++mi)
#pragma unroll
        for (int n = 0; n < 4; ++n)
#pragma unroll
            for (int j = 0; j < 4; ++j) acc[mi][n][j] = 0.f;

    // Per-thread LDSM base offsets
    const uint32_t a_row_off = (lane & 15) * ROW_BYTES + (lane >> 4) * 16;        // +k*2
    const uint32_t b_row_off = (((lane >> 4) & 1) * 8 + (lane & 7)) * ROW_BYTES
                               + (((lane >> 3) & 1) * 8) * 2;                      // +k*2

    // ---- producer body: cp.async tile `it` into stage `s`, noinc-arrive full
    auto produce = [&](int it, int s) {
        const int k0 = it * BK;
        const uint32_t As = sbase + s * STAGE_BYTES;
        const uint32_t Bs = As + A_STAGE_BYTES;
#pragma unroll
        for (int i = 0; i < 4; ++i) {           // A: 1024 16B chunks, 4/thread
            const int c = tid + i * 256;
            const int r = c >> 3, cc = c & 7;
            const uint32_t d = As + r * ROW_BYTES + cc * 16;
            const size_t gsrc = __cvta_generic_to_global(gA + (size_t)r * KDIM + k0 + cc * 8);
            asm volatile("cp.async.cg.shared.global [%0], [%1], 16;"
                         :: "r"(d), "l"(gsrc) : "memory");
        }
#pragma unroll
        for (int i = 0; i < 4; ++i) {           // B: 1024 chunks, 4/thread
            const int c = tid + i * 256;
            const int r = c >> 3, cc = c & 7;
            const uint32_t d = Bs + r * ROW_BYTES + cc * 16;
            const size_t gsrc = __cvta_generic_to_global(gW + (size_t)r * KDIM + k0 + cc * 8);
            asm volatile("cp.async.cg.shared.global [%0], [%1], 16;"
                         :: "r"(d), "l"(gsrc) : "memory");
        }
        CPASYNC_MBAR_ARRIVE_NOINC(full_a[s]);
    };

    // ---- prologue ------------------------------------------------------------
    int p_stage = 0, p_phase = 1;
#pragma unroll
    for (int it = 0; it < STAGES - 1; ++it) {
        MBAR_WAIT_PARITY(empty_a[p_stage], p_phase);  // passes immediately round 0
        produce(it, p_stage);
        if (++p_stage == STAGES) { p_stage = 0; p_phase ^= 1; }
    }

    int c_stage = 0, c_phase = 0;

    // ---- mainloop (R10 ordering: compute, then produce next) ----------------
    for (int it = 0; it < KITERS; ++it) {
        MBAR_WAIT_PARITY(full_a[c_stage], c_phase);

        const uint32_t As = sbase + c_stage * STAGE_BYTES;
        const uint32_t Bs = As + A_STAGE_BYTES;

#pragma unroll
        for (int ks = 0; ks < BK / 16; ++ks) {
            const uint32_t kb = ks * 32;  // bytes along k
            uint32_t a[4][4], b[2][4];
#pragma unroll
            for (int mi = 0; mi < 4; ++mi) {
                const uint32_t ad = As + (wm + mi * 16) * ROW_BYTES + a_row_off + kb;
                asm volatile("ldmatrix.sync.aligned.m8n8.x4.shared.b16 {%0,%1,%2,%3}, [%4];"
                             : "=r"(a[mi][0]), "=r"(a[mi][1]), "=r"(a[mi][2]), "=r"(a[mi][3])
                             : "r"(ad));
            }
#pragma unroll
            for (int nj = 0; nj < 2; ++nj) {
                const uint32_t bd = Bs + (wn + nj * 16) * ROW_BYTES + b_row_off + kb;
                asm volatile("ldmatrix.sync.aligned.m8n8.x4.shared.b16 {%0,%1,%2,%3}, [%4];"
                             : "=r"(b[nj][0]), "=r"(b[nj][1]), "=r"(b[nj][2]), "=r"(b[nj][3])
                             : "r"(bd));
            }
            // smem for this stage is dead after the LAST kstep's ldmatrix:
            // release it before the (register-only) MMAs.
            if (ks == BK / 16 - 1 && lane == 0) MBAR_ARRIVE(empty_a[c_stage]);
#pragma unroll
            for (int mi = 0; mi < 4; ++mi) {
#pragma unroll
                for (int n = 0; n < 4; ++n) {
                    float* c = acc[mi][n];
                    const uint32_t b0 = b[n >> 1][(n & 1) * 2];
                    const uint32_t b1 = b[n >> 1][(n & 1) * 2 + 1];
                    asm volatile(
                        "mma.sync.aligned.m16n8k16.row.col.f32.f16.f16.f32 "
                        "{%0,%1,%2,%3}, {%4,%5,%6,%7}, {%8,%9}, {%0,%1,%2,%3};"
                        : "+f"(c[0]), "+f"(c[1]), "+f"(c[2]), "+f"(c[3])
                        : "r"(a[mi][0]), "r"(a[mi][1]), "r"(a[mi][2]), "r"(a[mi][3]),
                          "r"(b0), "r"(b1));
                }
            }
        }

        if (++c_stage == STAGES) { c_stage = 0; c_phase ^= 1; }

        const int nt = it + (STAGES - 1);
        if (nt < KITERS) {
            MBAR_WAIT_PARITY(empty_a[p_stage], p_phase);
            produce(nt, p_stage);
            if (++p_stage == STAGES) { p_stage = 0; p_phase ^= 1; }
        }
    }

    // ---- epilogue: out = acc*sw + bias --------------------------------------
    const float swv = *swp;
#pragma unroll
    for (int mi = 0; mi < 4; ++mi) {
        const int mr = m0 + wm + mi * 16 + (lane >> 2);
        float* r0 = out + (size_t)mr * NDIM;
        float* r1 = out + (size_t)(mr + 8) * NDIM;
#pragma unroll
        for (int n = 0; n < 4; ++n) {
            const int nc = n0 + wn + n * 8 + (lane & 3) * 2;
            const float2 bv = *reinterpret_cast<const float2*>(bias + nc);
            float2 v0, v1;
            v0.x = acc[mi][n][0] * swv + bv.x;
            v0.y = acc[mi][n][1] * swv + bv.y;
            v1.x = acc[mi][n][2] * swv + bv.x;
            v1.y = acc[mi][n][3] * swv + bv.y;
            *reinterpret_cast<float2*>(r0 + nc) = v0;
            *reinterpret_cast<float2*>(r1 + nc) = v1;
        }
    }
}

// ---------------- launch -----------------------------------------------------
extern "C" void kernel_launch(void* const* d_in, const int* in_sizes, int n_in,
                              void* d_out, int out_size) {
    const float* x = (const float*)d_in[0];
    const int* qw = (const int*)d_in[1];
    const float* sw = (const float*)d_in[2];
    const float* bias = (const float*)d_in[3];
    float* out = (float*)d_out;
    (void)in_sizes; (void)n_in; (void)out_size;

    cudaFuncSetAttribute(gemm_kernel, cudaFuncAttributeMaxDynamicSharedMemorySize, SMEM_TOTAL);

    convert_w_kernel<<<(NDIM * (size_t)KDIM) / 4 / 256, 256>>>(qw);
    convert_x_kernel<<<((size_t)MDIM * KDIM) / 4 / 256, 256>>>(x);

    dim3 grid(NDIM / BN, MDIM / BM);  // (32, 64)
    gemm_kernel<<<grid, 256, SMEM_TOTAL>>>(out, sw, bias);
}

// round 16
// speedup vs baseline: 1.6860x; 1.0093x over previous
#include <cuda_runtime.h>
#include <cuda_fp16.h>
#include <cstdint>

// ============================================================================
// y[M,N] = x[M,K] @ (qw*sw)^T + bias   M=8192, N=4096, K=4096
// x fp32, qw int32 (int8 values), sw fp32 scalar, bias fp32[N], out fp32.
//
// compute_103 target (no tcgen05) => mma.sync.m16n8k16 fp16 / fp32 accum.
// Weights EXACT in fp16 (|q|<=128); x->fp16 gives rel_err ~2e-4 < 1e-3.
//
// R15 = exact R10 GEMM (best measured 628.8us; all scheduling variants since
// are neutral => at the HMMA issue floor ~8cyc/instr @NAT clocks) +
// conversions merged into ONE kernel (w-stream and x-stream overlap toward
// the 36us combined DRAM floor; removes a launch gap).
// ============================================================================

#define MDIM 8192
#define NDIM 4096
#define KDIM 4096

#define BM 128
#define BN 128
#define BK 64
#define STAGES 3
#define KITERS (KDIM / BK)          // 64

#define ROW_HALFS (BK + 8)           // 72 halfs = 144 B (conflict-free ldmatrix)
#define ROW_BYTES (ROW_HALFS * 2)
#define A_STAGE_BYTES (BM * ROW_BYTES)             // 18432
#define B_STAGE_BYTES (BN * ROW_BYTES)             // 18432
#define STAGE_BYTES (A_STAGE_BYTES + B_STAGE_BYTES)  // 36864
#define SMEM_TOTAL (STAGES * STAGE_BYTES)            // 110592 B -> 2 CTAs/SM

// ---------------- scratch (static device globals: allocation-free) ----------
__device__ __half g_xh[(size_t)MDIM * KDIM];  // 64 MB
__device__ __half g_w[(size_t)NDIM * KDIM];   // 32 MB

// ---------------- mbarrier helpers (sm_80+ generic PTX) ----------------------
#define MBAR_INIT(addr, count) \
    asm volatile("mbarrier.init.shared.b64 [%0], %1;" \
        :: "r"((uint32_t)(addr)), "r"((uint32_t)(count)) : "memory")

#define MBAR_ARRIVE(addr) \
    asm volatile("mbarrier.arrive.shared.b64 _, [%0];" :: "r"((uint32_t)(addr)) : "memory")

// NOINC: the completion arrive COUNTS against the init count (256).
#define CPASYNC_MBAR_ARRIVE_NOINC(addr) \
    asm volatile("cp.async.mbarrier.arrive.noinc.shared.b64 [%0];" \
        :: "r"((uint32_t)(addr)) : "memory")

#define MBAR_WAIT_PARITY(mbar_addr, phase_parity) do { \
    uint32_t _mbar = (uint32_t)(mbar_addr); \
    uint32_t _par = (uint32_t)(phase_parity); \
    uint32_t _done; \
    asm volatile( \
        "{\n\t.reg .pred p;\n\t" \
        "mbarrier.try_wait.parity.shared.b64 p, [%1], %2, 0x989680;\n\t" \
        "selp.b32 %0, 1, 0, p;\n\t}" \
        : "=r"(_done) : "r"(_mbar), "r"(_par) : "memory"); \
    if (!_done) { \
        asm volatile( \
            "{\n\t.reg .pred P1;\n\t" \
            "WL_%=:\n\t" \
            "mbarrier.try_wait.parity.shared.b64 P1, [%0], %1, 0x989680;\n\t" \
            "@P1 bra.uni WD_%=;\n\t" \
            "bra.uni WL_%=;\n\t" \
            "WD_%=:\n\t}" \
            :: "r"(_mbar), "r"(_par) : "memory"); \
    } \
} while (0)

// ---------------- merged conversion kernel -----------------------------------
// Chunks 0 .. NW4-1: one int4 of qw -> 4 halfs of g_w.
// Chunks NW4 .. NW4+NX4-1: one float4 of x -> 4 halfs of g_xh.
#define NW4 ((size_t)NDIM * KDIM / 4)   // 4,194,304
#define NX4 ((size_t)MDIM * KDIM / 4)   // 8,388,608

__global__ __launch_bounds__(256) void convert_all_kernel(
    const int* __restrict__ qw, const float* __restrict__ x) {
    const size_t t = (size_t)blockIdx.x * blockDim.x + threadIdx.x;
    if (t < NW4) {
        const int4 v = reinterpret_cast<const int4*>(qw)[t];
        __half2* w2 = reinterpret_cast<__half2*>(g_w);
        w2[2 * t + 0] = __floats2half2_rn((float)v.x, (float)v.y);
        w2[2 * t + 1] = __floats2half2_rn((float)v.z, (float)v.w);
    } else {
        const size_t i = t - NW4;
        const float4 v = reinterpret_cast<const float4*>(x)[i];
        __half2* xh2 = reinterpret_cast<__half2*>(g_xh);
        xh2[2 * i + 0] = __floats2half2_rn(v.x, v.y);
        xh2[2 * i + 1] = __floats2half2_rn(v.z, v.w);
    }
}

// ---------------- GEMM kernel (exact R10 structure) ---------------------------
__global__ __launch_bounds__(256, 2) void gemm_kernel(
    float* __restrict__ out,
    const float* __restrict__ swp,
    const float* __restrict__ bias) {
    extern __shared__ char smem[];
    __shared__ unsigned long long mb_full[STAGES];
    __shared__ unsigned long long mb_empty[STAGES];

    const int tid = threadIdx.x;
    const int lane = tid & 31;
    const int wid = tid >> 5;
    const int wm = (wid & 1) * 64;   // 2 warps in m, 64 rows each
    const int wn = (wid >> 1) * 32;  // 4 warps in n, 32 cols each
    const int m0 = blockIdx.y * BM;
    const int n0 = blockIdx.x * BN;

    const uint32_t sbase = (uint32_t)__cvta_generic_to_shared(smem);
    uint32_t full_a[STAGES], empty_a[STAGES];
#pragma unroll
    for (int s = 0; s < STAGES; ++s) {
        full_a[s] = (uint32_t)__cvta_generic_to_shared(&mb_full[s]);
        empty_a[s] = (uint32_t)__cvta_generic_to_shared(&mb_empty[s]);
    }

    if (tid == 0) {
#pragma unroll
        for (int s = 0; s < STAGES; ++s) {
            MBAR_INIT(full_a[s], 256);  // one NOINC completion-arrive per thread
            MBAR_INIT(empty_a[s], 8);   // one arrive per consumer warp
        }
    }
    __syncthreads();

    const __half* gA = g_xh + (size_t)m0 * KDIM;
    const __half* gW = g_w + (size_t)n0 * KDIM;
    const float swv = *swp;          // hoisted: off the epilogue critical path

    float acc[4][4][4];
#pragma unroll
    for (int mi = 0; mi < 4; ++mi)
#pragma unroll
        for (int n = 0; n < 4; ++n)
#pragma unroll
            for (int j = 0; j < 4; ++j) acc[mi][n][j] = 0.f;

    // Per-thread LDSM base offsets
    const uint32_t a_row_off = (lane & 15) * ROW_BYTES + (lane >> 4) * 16;        // +k*2
    const uint32_t b_row_off = (((lane >> 4) & 1) * 8 + (lane & 7)) * ROW_BYTES
                               + (((lane >> 3) & 1) * 8) * 2;                      // +k*2

    // ---- producer body: cp.async tile `it` into stage `s`, noinc-arrive full
    auto produce = [&](int it, int s) {
        const int k0 = it * BK;
        const uint32_t As = sbase + s * STAGE_BYTES;
        const uint32_t Bs = As + A_STAGE_BYTES;
#pragma unroll
        for (int i = 0; i < 4; ++i) {           // A: 1024 16B chunks, 4/thread
            const int c = tid + i * 256;
            const int r = c >> 3, cc = c & 7;
            const uint32_t d = As + r * ROW_BYTES + cc * 16;
            const size_t gsrc = __cvta_generic_to_global(gA + (size_t)r * KDIM + k0 + cc * 8);
            asm volatile("cp.async.cg.shared.global [%0], [%1], 16;"
                         :: "r"(d), "l"(gsrc) : "memory");
        }
#pragma unroll
        for (int i = 0; i < 4; ++i) {           // B: 1024 chunks, 4/thread
            const int c = tid + i * 256;
            const int r = c >> 3, cc = c & 7;
            const uint32_t d = Bs + r * ROW_BYTES + cc * 16;
            const size_t gsrc = __cvta_generic_to_global(gW + (size_t)r * KDIM + k0 + cc * 8);
            asm volatile("cp.async.cg.shared.global [%0], [%1], 16;"
                         :: "r"(d), "l"(gsrc) : "memory");
        }
        CPASYNC_MBAR_ARRIVE_NOINC(full_a[s]);
    };

    // ---- prologue ------------------------------------------------------------
    int p_stage = 0, p_phase = 1;
#pragma unroll
    for (int it = 0; it < STAGES - 1; ++it) {
        MBAR_WAIT_PARITY(empty_a[p_stage], p_phase);  // passes immediately round 0
        produce(it, p_stage);
        if (++p_stage == STAGES) { p_stage = 0; p_phase ^= 1; }
    }

    int c_stage = 0, c_phase = 0;

    // ---- mainloop (R10 ordering: compute, then produce next) ----------------
    for (int it = 0; it < KITERS; ++it) {
        MBAR_WAIT_PARITY(full_a[c_stage], c_phase);

        const uint32_t As = sbase + c_stage * STAGE_BYTES;
        const uint32_t Bs = As + A_STAGE_BYTES;

#pragma unroll
        for (int ks = 0; ks < BK / 16; ++ks) {
            const uint32_t kb = ks * 32;  // bytes along k
            uint32_t a[4][4], b[2][4];
#pragma unroll
            for (int mi = 0; mi < 4; ++mi) {
                const uint32_t ad = As + (wm + mi * 16) * ROW_BYTES + a_row_off + kb;
                asm volatile("ldmatrix.sync.aligned.m8n8.x4.shared.b16 {%0,%1,%2,%3}, [%4];"
                             : "=r"(a[mi][0]), "=r"(a[mi][1]), "=r"(a[mi][2]), "=r"(a[mi][3])
                             : "r"(ad));
            }
#pragma unroll
            for (int nj = 0; nj < 2; ++nj) {
                const uint32_t bd = Bs + (wn + nj * 16) * ROW_BYTES + b_row_off + kb;
                asm volatile("ldmatrix.sync.aligned.m8n8.x4.shared.b16 {%0,%1,%2,%3}, [%4];"
                             : "=r"(b[nj][0]), "=r"(b[nj][1]), "=r"(b[nj][2]), "=r"(b[nj][3])
                             : "r"(bd));
            }
#pragma unroll
            for (int mi = 0; mi < 4; ++mi) {
#pragma unroll
                for (int n = 0; n < 4; ++n) {
                    float* c = acc[mi][n];
                    const uint32_t b0 = b[n >> 1][(n & 1) * 2];
                    const uint32_t b1 = b[n >> 1][(n & 1) * 2 + 1];
                    asm volatile(
                        "mma.sync.aligned.m16n8k16.row.col.f32.f16.f16.f32 "
                        "{%0,%1,%2,%3}, {%4,%5,%6,%7}, {%8,%9}, {%0,%1,%2,%3};"
                        : "+f"(c[0]), "+f"(c[1]), "+f"(c[2]), "+f"(c[3])
                        : "r"(a[mi][0]), "r"(a[mi][1]), "r"(a[mi][2]), "r"(a[mi][3]),
                          "r"(b0), "r"(b1));
                }
            }
        }

        __syncwarp();
        if (lane == 0) MBAR_ARRIVE(empty_a[c_stage]);   // release stage (count 8)
        if (++c_stage == STAGES) { c_stage = 0; c_phase ^= 1; }

        const int nt = it + (STAGES - 1);
        if (nt < KITERS) {
            MBAR_WAIT_PARITY(empty_a[p_stage], p_phase);
            produce(nt, p_stage);
            if (++p_stage == STAGES) { p_stage = 0; p_phase ^= 1; }
        }
    }

    // ---- epilogue: out = acc*sw + bias --------------------------------------
#pragma unroll
    for (int mi = 0; mi < 4; ++mi) {
        const int mr = m0 + wm + mi * 16 + (lane >> 2);
        float* r0 = out + (size_t)mr * NDIM;
        float* r1 = out + (size_t)(mr + 8) * NDIM;
#pragma unroll
        for (int n = 0; n < 4; ++n) {
            const int nc = n0 + wn + n * 8 + (lane & 3) * 2;
            const float2 bv = *reinterpret_cast<const float2*>(bias + nc);
            float2 v0, v1;
            v0.x = acc[mi][n][0] * swv + bv.x;
            v0.y = acc[mi][n][1] * swv + bv.y;
            v1.x = acc[mi][n][2] * swv + bv.x;
            v1.y = acc[mi][n][3] * swv + bv.y;
            *reinterpret_cast<float2*>(r0 + nc) = v0;
            *reinterpret_cast<float2*>(r1 + nc) = v1;
        }
    }
}

// ---------------- launch -----------------------------------------------------
extern "C" void kernel_launch(void* const* d_in, const int* in_sizes, int n_in,
                              void* d_out, int out_size) {
    const float* x = (const float*)d_in[0];
    const int* qw = (const int*)d_in[1];
    const float* sw = (const float*)d_in[2];
    const float* bias = (const float*)d_in[3];
    float* out = (float*)d_out;
    (void)in_sizes; (void)n_in; (void)out_size;

    cudaFuncSetAttribute(gemm_kernel, cudaFuncAttributeMaxDynamicSharedMemorySize, SMEM_TOTAL);

    // Single merged conversion launch: 12,582,912 chunks (w then x) / 256
    convert_all_kernel<<<(int)((NW4 + NX4) / 256), 256>>>(qw, x);

    dim3 grid(NDIM / BN, MDIM / BM);  // (32, 64)
    gemm_kernel<<<grid, 256, SMEM_TOTAL>>>(out, sw, bias);
}